// round 2
// baseline (speedup 1.0000x reference)
#include <cuda_runtime.h>

// SSIM loss over [8,8,3,256,256] fp32 pred/target -> scalar (1 - mean ssim_map).
// Separable 11-tap Gaussian (zero-padded), fused 5-field conv + SSIM + reduction.

#define NPLANES 192        // 8*8*3 channel planes
#define HW      256
#define TS      32         // output tile
#define HALO    5
#define LW      42         // TS + 2*HALO
#define NBX     8
#define NBY     8
#define NBLOCKS (NPLANES * NBX * NBY)   // 12288

__device__ float g_partial[NBLOCKS];

// Gaussian weights, ws=11, sigma=1.5, normalized (hardcoded so ptxas gets FFMA-imm)
#define G0 0.00102838f
#define G1 0.00759876f
#define G2 0.03600077f
#define G3 0.10936070f
#define G4 0.21300548f
#define G5 0.26601173f

__global__ __launch_bounds__(256) void ssim_main_kernel(
    const float* __restrict__ pred, const float* __restrict__ tgt)
{
    __shared__ float sx[LW][LW];
    __shared__ float sy[LW][LW];
    __shared__ float hA[5][LW][TS];   // H-pass: x, y, xx, yy, xy
    __shared__ float wsum[8];

    const float G[11] = {G0, G1, G2, G3, G4, G5, G4, G3, G2, G1, G0};

    const int tid = threadIdx.x;
    const int p  = blockIdx.z;
    const int ox = blockIdx.x * TS - HALO;
    const int oy = blockIdx.y * TS - HALO;
    const float* __restrict__ px = pred + (size_t)p * HW * HW;
    const float* __restrict__ py = tgt  + (size_t)p * HW * HW;

    // Load tile + halo, clip to [0,1], zero outside image (zero padding)
    for (int i = tid; i < LW * LW; i += 256) {
        int r = i / LW;
        int c = i - r * LW;
        int gr = oy + r, gc = ox + c;
        float vx = 0.f, vy = 0.f;
        if ((unsigned)gr < HW && (unsigned)gc < HW) {
            int gi = gr * HW + gc;
            vx = __saturatef(px[gi]);
            vy = __saturatef(py[gi]);
        }
        sx[r][c] = vx;
        sy[r][c] = vy;
    }
    __syncthreads();

    // Horizontal pass over all LW rows x TS cols
    for (int i = tid; i < LW * TS; i += 256) {
        int r = i >> 5;
        int c = i & 31;
        float hx = 0.f, hy = 0.f, hxx = 0.f, hyy = 0.f, hxy = 0.f;
#pragma unroll
        for (int k = 0; k < 11; k++) {
            float vx = sx[r][c + k];
            float vy = sy[r][c + k];
            float tx = G[k] * vx;
            float ty = G[k] * vy;
            hx += tx;
            hy += ty;
            hxx = fmaf(tx, vx, hxx);
            hyy = fmaf(ty, vy, hyy);
            hxy = fmaf(tx, vy, hxy);
        }
        hA[0][r][c] = hx;
        hA[1][r][c] = hy;
        hA[2][r][c] = hxx;
        hA[3][r][c] = hyy;
        hA[4][r][c] = hxy;
    }
    __syncthreads();

    // Vertical pass + SSIM map + local sum
    float lsum = 0.f;
    for (int i = tid; i < TS * TS; i += 256) {
        int r = i >> 5;
        int c = i & 31;
        float mx = 0.f, my = 0.f, mxx = 0.f, myy = 0.f, mxy = 0.f;
#pragma unroll
        for (int k = 0; k < 11; k++) {
            mx  = fmaf(G[k], hA[0][r + k][c], mx);
            my  = fmaf(G[k], hA[1][r + k][c], my);
            mxx = fmaf(G[k], hA[2][r + k][c], mxx);
            myy = fmaf(G[k], hA[3][r + k][c], myy);
            mxy = fmaf(G[k], hA[4][r + k][c], mxy);
        }
        float mx2 = mx * mx;
        float my2 = my * my;
        float mxy2 = mx * my;
        float sx2 = fmaxf(mxx - mx2, 0.f);
        float sy2 = fmaxf(myy - my2, 0.f);
        float sxy = mxy - mxy2;
        float num = fmaf(2.f, mxy2, 1e-4f) * fmaf(2.f, sxy, 9e-4f);
        float den = (mx2 + my2 + 1e-4f) * (sx2 + sy2 + 9e-4f) + 1e-8f;
        lsum += __fdividef(num, den);
    }

    // Block reduction -> partial
#pragma unroll
    for (int off = 16; off; off >>= 1)
        lsum += __shfl_xor_sync(0xFFFFFFFFu, lsum, off);
    if ((tid & 31) == 0) wsum[tid >> 5] = lsum;
    __syncthreads();
    if (tid == 0) {
        float s = 0.f;
#pragma unroll
        for (int w = 0; w < 8; w++) s += wsum[w];
        g_partial[(blockIdx.z * NBY + blockIdx.y) * NBX + blockIdx.x] = s;
    }
}

__global__ __launch_bounds__(1024) void ssim_reduce_kernel(float* __restrict__ out)
{
    __shared__ double ws[32];
    const int tid = threadIdx.x;
    double s = 0.0;
    for (int i = tid; i < NBLOCKS; i += 1024)
        s += (double)g_partial[i];
#pragma unroll
    for (int off = 16; off; off >>= 1)
        s += __shfl_xor_sync(0xFFFFFFFFu, s, off);
    if ((tid & 31) == 0) ws[tid >> 5] = s;
    __syncthreads();
    if (tid < 32) {
        double v = ws[tid];
#pragma unroll
        for (int off = 16; off; off >>= 1)
            v += __shfl_xor_sync(0xFFFFFFFFu, v, off);
        if (tid == 0)
            out[0] = 1.0f - (float)(v / (double)(NPLANES * HW * HW));
    }
}

extern "C" void kernel_launch(void* const* d_in, const int* in_sizes, int n_in,
                              void* d_out, int out_size)
{
    const float* pred = (const float*)d_in[0];
    const float* tgt  = (const float*)d_in[1];
    float* out = (float*)d_out;

    dim3 grid(NBX, NBY, NPLANES);
    ssim_main_kernel<<<grid, 256>>>(pred, tgt);
    ssim_reduce_kernel<<<1, 1024>>>(out);
}

// round 4
// speedup vs baseline: 1.0740x; 1.0740x over previous
#include <cuda_runtime.h>

// SSIM loss over [8,8,3,256,256] fp32 -> scalar.
// Vertical-first separable 11-tap Gaussian, packed f32x2 vertical pass,
// LDS.64 + symmetric-fold horizontal pass, fused SSIM + 2-stage reduction.

typedef unsigned long long u64;

#define NPLANES 192
#define HW      256
#define TSX     64
#define TSY     32
#define LWX     76          // TSX + 2*5 halo + 2 align pad
#define LWY     42          // TSY + 2*5 halo
#define SST     80          // shared stride (floats) for sx/sy: conflict-tuned
#define HST     76          // shared stride (floats) for hA
#define NBX     4
#define NBY     8
#define NBLOCKS (NPLANES * NBX * NBY)   // 6144

__device__ float g_partial[NBLOCKS];

// Gaussian ws=11 sigma=1.5 normalized
#define G0 0.00102838f
#define G1 0.00759876f
#define G2 0.03600077f
#define G3 0.10936070f
#define G4 0.21300548f
#define G5 0.26601173f

__device__ __forceinline__ u64 pk2(float lo, float hi) {
    u64 r; asm("mov.b64 %0, {%1, %2};" : "=l"(r) : "f"(lo), "f"(hi)); return r;
}
__device__ __forceinline__ u64 fma2(u64 a, u64 b, u64 c) {
    u64 d; asm("fma.rn.f32x2 %0, %1, %2, %3;" : "=l"(d) : "l"(a), "l"(b), "l"(c)); return d;
}
__device__ __forceinline__ u64 mul2(u64 a, u64 b) {
    u64 d; asm("mul.rn.f32x2 %0, %1, %2;" : "=l"(d) : "l"(a), "l"(b)); return d;
}
__device__ __forceinline__ u64 add2(u64 a, u64 b) {
    u64 d; asm("add.rn.f32x2 %0, %1, %2;" : "=l"(d) : "l"(a), "l"(b)); return d;
}

__device__ __forceinline__ float ssim_px(float mx, float my, float mxx,
                                         float myy, float mxy) {
    float mx2 = mx * mx;
    float my2 = my * my;
    float mab = mx * my;
    float sx2 = fmaxf(mxx - mx2, 0.f);
    float sy2 = fmaxf(myy - my2, 0.f);
    float sxy = mxy - mab;
    float num = fmaf(2.f, mab, 1e-4f) * fmaf(2.f, sxy, 9e-4f);
    float den = (mx2 + my2 + 1e-4f) * (sx2 + sy2 + 9e-4f) + 1e-8f;
    return __fdividef(num, den);
}

__global__ __launch_bounds__(256) void ssim_main_kernel(
    const float* __restrict__ pred, const float* __restrict__ tgt)
{
    extern __shared__ float sh[];
    float* sx = sh;                      // [LWY][SST]
    float* sy = sh + LWY * SST;          // [LWY][SST]
    float* hA = sh + 2 * LWY * SST;      // [5][TSY][HST]
    __shared__ float wsum[8];

    const float Gv[6] = {G0, G1, G2, G3, G4, G5};

    const int tid = threadIdx.x;
    const int bx = blockIdx.x, by = blockIdx.y, p = blockIdx.z;
    const float* __restrict__ px = pred + (size_t)p * HW * HW;
    const float* __restrict__ py = tgt  + (size_t)p * HW * HW;
    const int gx0 = bx * TSX - 5;
    const int gy0 = by * TSY - 5;

    // ---- Load tile + halo, clip, zero-pad outside image ----
    for (int i = tid; i < LWY * LWX; i += 256) {
        int r = i / LWX;
        int c = i - r * LWX;
        int gr = gy0 + r, gc = gx0 + c;
        float vx = 0.f, vy = 0.f;
        if ((unsigned)gr < HW && (unsigned)gc < HW) {
            int gi = gr * HW + gc;
            vx = __saturatef(px[gi]);
            vy = __saturatef(py[gi]);
        }
        sx[r * SST + c] = vx;
        sy[r * SST + c] = vy;
    }
    __syncthreads();

    // ---- Vertical pass: packed f32x2, on-the-fly products ----
    u64 gg[6];
#pragma unroll
    for (int m = 0; m < 6; m++) gg[m] = pk2(Gv[m], Gv[m]);

    const int vrow = tid >> 3;           // 0..31 (output row)
#pragma unroll
    for (int it = 0; it < 5; it++) {
        int pc = (tid & 7) + 8 * it;     // 0..39 pair index
        if (pc < 38) {
            int s = 2 * pc;
            u64 vx = 0, vy = 0, vxx = 0, vyy = 0, vxy = 0;
#pragma unroll
            for (int k = 0; k < 11; k++) {
                int m = (k < 6) ? k : 10 - k;
                u64 xv = *(const u64*)&sx[(vrow + k) * SST + s];
                u64 yv = *(const u64*)&sy[(vrow + k) * SST + s];
                u64 tx = mul2(gg[m], xv);
                u64 ty = mul2(gg[m], yv);
                vx = add2(vx, tx);
                vy = add2(vy, ty);
                vxx = fma2(tx, xv, vxx);
                vyy = fma2(ty, yv, vyy);
                vxy = fma2(tx, yv, vxy);
            }
            int hb = vrow * HST + s;
            *(u64*)&hA[0 * TSY * HST + hb] = vx;
            *(u64*)&hA[1 * TSY * HST + hb] = vy;
            *(u64*)&hA[2 * TSY * HST + hb] = vxx;
            *(u64*)&hA[3 * TSY * HST + hb] = vyy;
            *(u64*)&hA[4 * TSY * HST + hb] = vxy;
        }
    }
    __syncthreads();

    // ---- Horizontal pass + SSIM (2 output px per task) ----
    float lsum = 0.f;
#pragma unroll
    for (int it = 0; it < 4; it++) {
        int row = (tid >> 5) + 8 * it;   // 0..31
        int j = (tid & 31) * 2;          // 0..62 (even output col)
        float o0[5], o1[5];
#pragma unroll
        for (int f = 0; f < 5; f++) {
            const float* hb = &hA[(f * TSY + row) * HST + j];
            float v[12];
#pragma unroll
            for (int q = 0; q < 6; q++) {
                float2 t = *(const float2*)&hb[2 * q];
                v[2 * q]     = t.x;
                v[2 * q + 1] = t.y;
            }
            float a0 = Gv[5] * v[5];
            float a1 = Gv[5] * v[6];
#pragma unroll
            for (int k = 0; k < 5; k++) {
                a0 = fmaf(Gv[k], v[k] + v[10 - k], a0);
                a1 = fmaf(Gv[k], v[k + 1] + v[11 - k], a1);
            }
            o0[f] = a0;
            o1[f] = a1;
        }
        lsum += ssim_px(o0[0], o0[1], o0[2], o0[3], o0[4]);
        lsum += ssim_px(o1[0], o1[1], o1[2], o1[3], o1[4]);
    }

    // ---- Block reduction -> partial ----
#pragma unroll
    for (int off = 16; off; off >>= 1)
        lsum += __shfl_xor_sync(0xFFFFFFFFu, lsum, off);
    if ((tid & 31) == 0) wsum[tid >> 5] = lsum;
    __syncthreads();
    if (tid == 0) {
        float s = 0.f;
#pragma unroll
        for (int w = 0; w < 8; w++) s += wsum[w];
        g_partial[(blockIdx.z * NBY + by) * NBX + bx] = s;
    }
}

__global__ __launch_bounds__(1024) void ssim_reduce_kernel(float* __restrict__ out)
{
    __shared__ double ws[32];
    const int tid = threadIdx.x;
    double s = 0.0;
    for (int i = tid; i < NBLOCKS; i += 1024)
        s += (double)g_partial[i];
#pragma unroll
    for (int off = 16; off; off >>= 1)
        s += __shfl_xor_sync(0xFFFFFFFFu, s, off);
    if ((tid & 31) == 0) ws[tid >> 5] = s;
    __syncthreads();
    if (tid < 32) {
        double v = ws[tid];
#pragma unroll
        for (int off = 16; off; off >>= 1)
            v += __shfl_xor_sync(0xFFFFFFFFu, v, off);
        if (tid == 0)
            out[0] = 1.0f - (float)(v / (double)(NPLANES * HW * HW));
    }
}

extern "C" void kernel_launch(void* const* d_in, const int* in_sizes, int n_in,
                              void* d_out, int out_size)
{
    const float* pred = (const float*)d_in[0];
    const float* tgt  = (const float*)d_in[1];
    float* out = (float*)d_out;

    const int smem = (2 * LWY * SST + 5 * TSY * HST) * sizeof(float);  // 75,520 B
    cudaFuncSetAttribute(ssim_main_kernel,
                         cudaFuncAttributeMaxDynamicSharedMemorySize, smem);

    dim3 grid(NBX, NBY, NPLANES);
    ssim_main_kernel<<<grid, 256, smem>>>(pred, tgt);
    ssim_reduce_kernel<<<1, 1024>>>(out);
}

// round 6
// speedup vs baseline: 1.4121x; 1.3148x over previous
#include <cuda_runtime.h>

// SSIM loss over [8,8,3,256,256] fp32 -> scalar.
// Register-sliding-window vertical 11-tap Gaussian (FFMA-imm), swizzled smem
// row-chunk buffer for horizontal pass, fused SSIM + 2-stage reduction.

#define NPLANES 192
#define HW      256
#define TSY     32          // output rows per block
#define CH      8           // chunk rows
#define NCH     4
#define FST     272         // field row stride in floats (8 zero-pad each side)
#define NBLOCKS (NPLANES * 8)   // 1536

__device__ float g_partial[NBLOCKS];

// Gaussian ws=11 sigma=1.5 normalized
#define G0 0.00102838f
#define G1 0.00759876f
#define G2 0.03600077f
#define G3 0.10936070f
#define G4 0.21300548f
#define G5 0.26601173f

#define SWZ(b) ((b) ^ (((b) >> 3) & 0x70))

__device__ __forceinline__ float ssim_px(float mx, float my, float mxx,
                                         float myy, float mxy) {
    float mx2 = mx * mx;
    float my2 = my * my;
    float mab = mx * my;
    float sx2 = fmaxf(mxx - mx2, 0.f);
    float sy2 = fmaxf(myy - my2, 0.f);
    float sxy = mxy - mab;
    float num = fmaf(2.f, mab, 1e-4f) * fmaf(2.f, sxy, 9e-4f);
    float den = (mx2 + my2 + 1e-4f) * (sx2 + sy2 + 9e-4f) + 1e-8f;
    return __fdividef(num, den);
}

__global__ __launch_bounds__(256, 1) void ssim_main_kernel(
    const float* __restrict__ pred, const float* __restrict__ tgt)
{
    __shared__ float fbuf[5 * CH * FST];   // 43,520 B, swizzled layout
    __shared__ float wsum[8];

    const float G[11] = {G0, G1, G2, G3, G4, G5, G4, G3, G2, G1, G0};

    const int t = threadIdx.x;             // owns image column t
    const int strip = blockIdx.x;          // 0..7
    const int p = blockIdx.y;              // plane
    const float* __restrict__ px = pred + (size_t)p * HW * HW;
    const float* __restrict__ py = tgt  + (size_t)p * HW * HW;
    const int gy0 = strip * TSY;

    // Zero entire field buffer once (covers the zero-pad columns; interior is
    // overwritten before every read).
    for (int i = t; i < 5 * CH * FST; i += 256) fbuf[i] = 0.f;

    // Sliding windows (input rows base..base+17 for current chunk)
    float wx[18], wy[18], wxx[18], wyy[18], wxy[18];

    // Preload rows gy0-5 .. gy0+4 -> w[0..9]
#pragma unroll
    for (int j = 0; j < 10; j++) {
        int r = gy0 - 5 + j;
        float x = 0.f, y = 0.f;
        if ((unsigned)r < HW) {
            x = __saturatef(px[r * HW + t]);
            y = __saturatef(py[r * HW + t]);
        }
        wx[j] = x; wy[j] = y;
        wxx[j] = x * x; wyy[j] = y * y; wxy[j] = x * y;
    }
    // Prefetch chunk 0's new rows gy0+5 .. gy0+12
    float pfx[8], pfy[8];
#pragma unroll
    for (int j = 0; j < 8; j++) {
        int r = gy0 + 5 + j;
        float x = 0.f, y = 0.f;
        if (r < HW) {
            x = __saturatef(px[r * HW + t]);
            y = __saturatef(py[r * HW + t]);
        }
        pfx[j] = x; pfy[j] = y;
    }

    const int hrow = t >> 5;               // H-pass: warp = one chunk row
    const int c0 = (t & 31) * 8;           // 8 output px per thread
    float lsum = 0.f;

    for (int cc = 0; cc < NCH; cc++) {
        // Commit prefetched rows into window slots 10..17
#pragma unroll
        for (int j = 0; j < 8; j++) {
            float x = pfx[j], y = pfy[j];
            wx[10 + j] = x; wy[10 + j] = y;
            wxx[10 + j] = x * x; wyy[10 + j] = y * y; wxy[10 + j] = x * y;
        }
        // Prefetch next chunk's rows (in flight across V-conv + H-pass)
#pragma unroll
        for (int j = 0; j < 8; j++) {
            int r = gy0 + 13 + cc * 8 + j;
            float x = 0.f, y = 0.f;
            if (r < HW) {
                x = __saturatef(px[r * HW + t]);
                y = __saturatef(py[r * HW + t]);
            }
            pfx[j] = x; pfy[j] = y;
        }

        // Vertical conv: 8 output rows, 55 FFMA-imm each; store to swizzled smem
#pragma unroll
        for (int i = 0; i < 8; i++) {
            float ax = 0.f, ay = 0.f, axx = 0.f, ayy = 0.f, axy = 0.f;
#pragma unroll
            for (int k = 0; k < 11; k++) {
                ax  = fmaf(G[k], wx [i + k], ax);
                ay  = fmaf(G[k], wy [i + k], ay);
                axx = fmaf(G[k], wxx[i + k], axx);
                ayy = fmaf(G[k], wyy[i + k], ayy);
                axy = fmaf(G[k], wxy[i + k], axy);
            }
            int b0 = ((0 * CH + i) * FST + 8 + t) * 4;
            int b1 = ((1 * CH + i) * FST + 8 + t) * 4;
            int b2 = ((2 * CH + i) * FST + 8 + t) * 4;
            int b3 = ((3 * CH + i) * FST + 8 + t) * 4;
            int b4 = ((4 * CH + i) * FST + 8 + t) * 4;
            *(float*)((char*)fbuf + SWZ(b0)) = ax;
            *(float*)((char*)fbuf + SWZ(b1)) = ay;
            *(float*)((char*)fbuf + SWZ(b2)) = axx;
            *(float*)((char*)fbuf + SWZ(b3)) = ayy;
            *(float*)((char*)fbuf + SWZ(b4)) = axy;
        }
        __syncthreads();

        // Horizontal conv + SSIM: 8 px per thread, LDS.128 swizzled loads
        float hv[5][8];
#pragma unroll
        for (int f = 0; f < 5; f++) {
            float v[24];                   // cols c0-8 .. c0+15
#pragma unroll
            for (int m = 0; m < 6; m++) {
                int b = ((f * CH + hrow) * FST + c0 + 4 * m) * 4;
                float4 q4 = *(const float4*)((const char*)fbuf + SWZ(b));
                v[4 * m + 0] = q4.x; v[4 * m + 1] = q4.y;
                v[4 * m + 2] = q4.z; v[4 * m + 3] = q4.w;
            }
#pragma unroll
            for (int q = 0; q < 8; q++) {
                float a = 0.f;
#pragma unroll
                for (int k = 0; k < 11; k++)
                    a = fmaf(G[k], v[3 + q + k], a);
                hv[f][q] = a;
            }
        }
#pragma unroll
        for (int q = 0; q < 8; q++)
            lsum += ssim_px(hv[0][q], hv[1][q], hv[2][q], hv[3][q], hv[4][q]);
        __syncthreads();

        // Slide windows down 8 rows
#pragma unroll
        for (int j = 0; j < 10; j++) {
            wx [j] = wx [j + 8];
            wy [j] = wy [j + 8];
            wxx[j] = wxx[j + 8];
            wyy[j] = wyy[j + 8];
            wxy[j] = wxy[j + 8];
        }
    }

    // Block reduction -> partial
#pragma unroll
    for (int off = 16; off; off >>= 1)
        lsum += __shfl_xor_sync(0xFFFFFFFFu, lsum, off);
    if ((t & 31) == 0) wsum[t >> 5] = lsum;
    __syncthreads();
    if (t == 0) {
        float s = 0.f;
#pragma unroll
        for (int w = 0; w < 8; w++) s += wsum[w];
        g_partial[p * 8 + strip] = s;
    }
}

__global__ __launch_bounds__(1024) void ssim_reduce_kernel(float* __restrict__ out)
{
    __shared__ double ws[32];
    const int tid = threadIdx.x;
    double s = 0.0;
    for (int i = tid; i < NBLOCKS; i += 1024)
        s += (double)g_partial[i];
#pragma unroll
    for (int off = 16; off; off >>= 1)
        s += __shfl_xor_sync(0xFFFFFFFFu, s, off);
    if ((tid & 31) == 0) ws[tid >> 5] = s;
    __syncthreads();
    if (tid < 32) {
        double v = ws[tid];
#pragma unroll
        for (int off = 16; off; off >>= 1)
            v += __shfl_xor_sync(0xFFFFFFFFu, v, off);
        if (tid == 0)
            out[0] = 1.0f - (float)(v / (double)(NPLANES * HW * HW));
    }
}

extern "C" void kernel_launch(void* const* d_in, const int* in_sizes, int n_in,
                              void* d_out, int out_size)
{
    const float* pred = (const float*)d_in[0];
    const float* tgt  = (const float*)d_in[1];
    float* out = (float*)d_out;

    dim3 grid(8, NPLANES);
    ssim_main_kernel<<<grid, 256>>>(pred, tgt);
    ssim_reduce_kernel<<<1, 1024>>>(out);
}